// round 9
// baseline (speedup 1.0000x reference)
#include <cuda_runtime.h>
#include <cstdint>

// Problem constants (fixed by the reference)
#define N_TOKENS  131072
#define HIDDEN    2048
#define N_RANKS   8
#define N_EXPERTS 16
#define NSEG (N_RANKS * N_EXPERTS)   // 128
#define VEC_PER_ROW (HIDDEN / 4)     // 512 float4
#define ROWS_PER_BLOCK 4

// d_out float layout:
//   [0, N_TOKENS*HIDDEN)   permute_tokens
//   [+N_TOKENS)            permute_per_token_scales
//   [+N_TOKENS)            idx (as float, exact: < 2^24)
//   [+N_EXPERTS)           expert_token_num (as float)
#define OFF_SCALES ((size_t)N_TOKENS * HIDDEN)
#define OFF_IDX    (OFF_SCALES + N_TOKENS)
#define OFF_ETN    (OFF_IDX + N_TOKENS)

__device__ __forceinline__ int warp_exscan(int v, int lane) {
    int inc = v;
    #pragma unroll
    for (int o = 1; o < 32; o <<= 1) {
        int n = __shfl_up_sync(0xffffffffu, inc, o);
        if (lane >= o) inc += n;
    }
    return inc - v;   // exclusive
}

// ---------------------------------------------------------------------------
// Single fused one-shot kernel: 32768 blocks x 256 threads, 4 rows per block.
// Prologue: warp 0 builds both 128-entry exclusive-prefix tables via a
// register scan (4 entries/lane + shfl exscan) — ONE __syncthreads total.
// Then: redundant 7-step smem binary search per thread (x4 rows),
// 8 front-batched LDG.128 -> 8 STG.128 per thread, scale/idx inline.
// ---------------------------------------------------------------------------
__global__ void __launch_bounds__(256, 4)
k_fused(const float4* __restrict__ tokens,
        const int*    __restrict__ counts,
        const float*  __restrict__ scales,
        float*        __restrict__ out) {
    __shared__ int s_in_start[NSEG];
    __shared__ int s_out_start[NSEG + 1];

    const int t = threadIdx.x;
    float4* __restrict__ out4 = (float4*)out;

    if (t < 32) {
        const int base = t * 4;
        // table A: input order (flat r*E+e) — contiguous, one LDG.128
        const int4 av = __ldg((const int4*)(counts + base));
        // table B: output order s = e*R+r  ->  count index (s&7)*E + (s>>3)
        const int b0 = __ldg(&counts[((base + 0) & 7) * N_EXPERTS + ((base + 0) >> 3)]);
        const int b1 = __ldg(&counts[((base + 1) & 7) * N_EXPERTS + ((base + 1) >> 3)]);
        const int b2 = __ldg(&counts[((base + 2) & 7) * N_EXPERTS + ((base + 2) >> 3)]);
        const int b3 = __ldg(&counts[((base + 3) & 7) * N_EXPERTS + ((base + 3) >> 3)]);

        const int sumA = av.x + av.y + av.z + av.w;
        const int sumB = b0 + b1 + b2 + b3;
        int exA = warp_exscan(sumA, t);
        int exB = warp_exscan(sumB, t);

        s_in_start[base + 0] = exA;
        s_in_start[base + 1] = exA + av.x;
        s_in_start[base + 2] = exA + av.x + av.y;
        s_in_start[base + 3] = exA + av.x + av.y + av.z;

        s_out_start[base + 0] = exB;
        s_out_start[base + 1] = exB + b0;
        s_out_start[base + 2] = exB + b0 + b1;
        s_out_start[base + 3] = exB + b0 + b1 + b2;
        if (t == 31) s_out_start[NSEG] = N_TOKENS;
    }
    // expert_token_num (block 0, warp 1 — overlaps warp 0's scan)
    if (blockIdx.x == 0 && t >= 32 && t < 32 + N_EXPERTS) {
        const int e = t - 32;
        int sum = 0;
        #pragma unroll
        for (int r = 0; r < N_RANKS; ++r) sum += __ldg(&counts[r * N_EXPERTS + e]);
        out[OFF_ETN + e] = (float)sum;
    }
    __syncthreads();   // the ONLY barrier

    const int row0 = blockIdx.x * ROWS_PER_BLOCK;

    // Every thread searches all 4 rows redundantly (smem broadcast reads).
    int src[ROWS_PER_BLOCK];
    #pragma unroll
    for (int k = 0; k < ROWS_PER_BLOCK; ++k) {
        const int row = row0 + k;
        int lo = 0, hi = NSEG;
        #pragma unroll 7
        while (hi - lo > 1) {
            int mid = (lo + hi) >> 1;
            if (s_out_start[mid] <= row) lo = mid; else hi = mid;
        }
        const int e = lo >> 3;            // lo / N_RANKS
        const int r = lo & 7;             // lo % N_RANKS
        src[k] = s_in_start[r * N_EXPERTS + e] + (row - s_out_start[lo]);
    }

    // 8 independent front-batched loads (2 per row).
    float4 v[2 * ROWS_PER_BLOCK];
    #pragma unroll
    for (int k = 0; k < ROWS_PER_BLOCK; ++k) {
        const float4* __restrict__ in = tokens + (size_t)src[k] * VEC_PER_ROW;
        v[2 * k + 0] = __ldg(&in[t]);
        v[2 * k + 1] = __ldg(&in[t + 256]);
    }

    // Scale + idx inline (threads 0..3, one row each).
    if (t < ROWS_PER_BLOCK) {
        const int row = row0 + t;
        const int s   = src[t];
        out[OFF_SCALES + row] = __ldg(&scales[s]);
        out[OFF_IDX + row]    = (float)s;
    }

    #pragma unroll
    for (int k = 0; k < ROWS_PER_BLOCK; ++k) {
        float4* __restrict__ o = out4 + (size_t)(row0 + k) * VEC_PER_ROW;
        o[t]       = v[2 * k + 0];
        o[t + 256] = v[2 * k + 1];
    }
}

// ---------------------------------------------------------------------------
extern "C" void kernel_launch(void* const* d_in, const int* in_sizes, int n_in,
                              void* d_out, int out_size) {
    const float* tokens = (const float*)d_in[0];
    const int*   counts = (const int*)d_in[1];     // [N_RANKS, N_EXPERTS]
    const float* scales = (const float*)d_in[2];
    // d_in[3] = expert_token_num_type (1), d_in[4] = idx_type (0) — fixed.
    float* out = (float*)d_out;

    k_fused<<<N_TOKENS / ROWS_PER_BLOCK, 256>>>((const float4*)tokens, counts, scales, out);
}

// round 10
// speedup vs baseline: 1.0023x; 1.0023x over previous
#include <cuda_runtime.h>
#include <cstdint>

// Problem constants (fixed by the reference)
#define N_TOKENS  131072
#define HIDDEN    2048
#define N_RANKS   8
#define N_EXPERTS 16
#define NSEG (N_RANKS * N_EXPERTS)   // 128
#define VEC_PER_ROW (HIDDEN / 4)     // 512 float4

// d_out float layout:
//   [0, N_TOKENS*HIDDEN)   permute_tokens
//   [+N_TOKENS)            permute_per_token_scales
//   [+N_TOKENS)            idx (as float, exact: < 2^24)
//   [+N_EXPERTS)           expert_token_num (as float)
#define OFF_SCALES ((size_t)N_TOKENS * HIDDEN)
#define OFF_IDX    (OFF_SCALES + N_TOKENS)
#define OFF_ETN    (OFF_IDX + N_TOKENS)

__device__ __forceinline__ int warp_exscan(int v, int lane) {
    int inc = v;
    #pragma unroll
    for (int o = 1; o < 32; o <<= 1) {
        int n = __shfl_up_sync(0xffffffffu, inc, o);
        if (lane >= o) inc += n;
    }
    return inc - v;   // exclusive
}

// ---------------------------------------------------------------------------
// Single fused one-shot kernel: 65536 blocks x 256 threads, 2 rows per block
// (the proven R8 structure: regs 32, occ ~85%). Prologue: warp 0 builds both
// 128-entry exclusive-prefix tables via a shfl register scan — ONE barrier.
// NEW vs R8: streaming cache hints. Token rows are read once and written
// once, never reused -> __ldcs / __stcs (evict-first) keep them from
// thrashing L2.
// ---------------------------------------------------------------------------
__global__ void __launch_bounds__(256, 8)
k_fused(const float4* __restrict__ tokens,
        const int*    __restrict__ counts,
        const float*  __restrict__ scales,
        float*        __restrict__ out) {
    __shared__ int s_in_start[NSEG];
    __shared__ int s_out_start[NSEG + 1];

    const int t = threadIdx.x;
    float4* __restrict__ out4 = (float4*)out;

    if (t < 32) {
        const int base = t * 4;
        // table A: input order (flat r*E+e) — contiguous, one LDG.128
        const int4 av = __ldg((const int4*)(counts + base));
        // table B: output order s = e*R+r  ->  count index (s&7)*E + (s>>3)
        const int b0 = __ldg(&counts[((base + 0) & 7) * N_EXPERTS + ((base + 0) >> 3)]);
        const int b1 = __ldg(&counts[((base + 1) & 7) * N_EXPERTS + ((base + 1) >> 3)]);
        const int b2 = __ldg(&counts[((base + 2) & 7) * N_EXPERTS + ((base + 2) >> 3)]);
        const int b3 = __ldg(&counts[((base + 3) & 7) * N_EXPERTS + ((base + 3) >> 3)]);

        const int sumA = av.x + av.y + av.z + av.w;
        const int sumB = b0 + b1 + b2 + b3;
        int exA = warp_exscan(sumA, t);
        int exB = warp_exscan(sumB, t);

        s_in_start[base + 0] = exA;
        s_in_start[base + 1] = exA + av.x;
        s_in_start[base + 2] = exA + av.x + av.y;
        s_in_start[base + 3] = exA + av.x + av.y + av.z;

        s_out_start[base + 0] = exB;
        s_out_start[base + 1] = exB + b0;
        s_out_start[base + 2] = exB + b0 + b1;
        s_out_start[base + 3] = exB + b0 + b1 + b2;
        if (t == 31) s_out_start[NSEG] = N_TOKENS;
    }
    // expert_token_num (block 0, warp 1 — overlaps warp 0's scan)
    if (blockIdx.x == 0 && t >= 32 && t < 32 + N_EXPERTS) {
        const int e = t - 32;
        int sum = 0;
        #pragma unroll
        for (int r = 0; r < N_RANKS; ++r) sum += __ldg(&counts[r * N_EXPERTS + e]);
        out[OFF_ETN + e] = (float)sum;
    }
    __syncthreads();   // the ONLY barrier

    const int row0 = blockIdx.x * 2;

    // Every thread searches both rows redundantly (smem broadcast reads).
    int src[2];
    #pragma unroll
    for (int k = 0; k < 2; ++k) {
        const int row = row0 + k;
        int lo = 0, hi = NSEG;
        #pragma unroll 7
        while (hi - lo > 1) {
            int mid = (lo + hi) >> 1;
            if (s_out_start[mid] <= row) lo = mid; else hi = mid;
        }
        const int e = lo >> 3;            // lo / N_RANKS
        const int r = lo & 7;             // lo % N_RANKS
        src[k] = s_in_start[r * N_EXPERTS + e] + (row - s_out_start[lo]);
    }

    const float4* __restrict__ in0 = tokens + (size_t)src[0] * VEC_PER_ROW;
    const float4* __restrict__ in1 = tokens + (size_t)src[1] * VEC_PER_ROW;
    float4* __restrict__ o0 = out4 + (size_t)row0 * VEC_PER_ROW;
    float4* __restrict__ o1 = o0 + VEC_PER_ROW;

    // 4 independent front-batched streaming loads (read-once).
    float4 a = __ldcs(&in0[t]);
    float4 b = __ldcs(&in0[t + 256]);
    float4 c = __ldcs(&in1[t]);
    float4 d = __ldcs(&in1[t + 256]);

    // Scale + idx inline (threads 0/1, one row each).
    if (t < 2) {
        const int row = row0 + t;
        const int s   = src[t];
        out[OFF_SCALES + row] = __ldg(&scales[s]);
        out[OFF_IDX + row]    = (float)s;
    }

    // Streaming stores (write-once, never re-read).
    __stcs(&o0[t],       a);
    __stcs(&o0[t + 256], b);
    __stcs(&o1[t],       c);
    __stcs(&o1[t + 256], d);
}

// ---------------------------------------------------------------------------
extern "C" void kernel_launch(void* const* d_in, const int* in_sizes, int n_in,
                              void* d_out, int out_size) {
    const float* tokens = (const float*)d_in[0];
    const int*   counts = (const int*)d_in[1];     // [N_RANKS, N_EXPERTS]
    const float* scales = (const float*)d_in[2];
    // d_in[3] = expert_token_num_type (1), d_in[4] = idx_type (0) — fixed.
    float* out = (float*)d_out;

    k_fused<<<N_TOKENS / 2, 256>>>((const float4*)tokens, counts, scales, out);
}

// round 12
// speedup vs baseline: 1.0042x; 1.0019x over previous
#include <cuda_runtime.h>
#include <cstdint>

// Problem constants (fixed by the reference)
#define N_TOKENS  131072
#define HIDDEN    2048
#define N_RANKS   8
#define N_EXPERTS 16
#define NSEG (N_RANKS * N_EXPERTS)   // 128
#define VEC_PER_ROW (HIDDEN / 4)     // 512 float4

// d_out float layout:
//   [0, N_TOKENS*HIDDEN)   permute_tokens
//   [+N_TOKENS)            permute_per_token_scales
//   [+N_TOKENS)            idx (as float, exact: < 2^24)
//   [+N_EXPERTS)           expert_token_num (as float)
#define OFF_SCALES ((size_t)N_TOKENS * HIDDEN)
#define OFF_IDX    (OFF_SCALES + N_TOKENS)
#define OFF_ETN    (OFF_IDX + N_TOKENS)

__device__ __forceinline__ int warp_exscan(int v, int lane) {
    int inc = v;
    #pragma unroll
    for (int o = 1; o < 32; o <<= 1) {
        int n = __shfl_up_sync(0xffffffffu, inc, o);
        if (lane >= o) inc += n;
    }
    return inc - v;   // exclusive
}

// ---------------------------------------------------------------------------
// Single fused one-shot kernel: 65536 blocks x 256 threads, 2 rows per block.
// Prologue: warp 0 builds both 128-entry exclusive-prefix tables via a shfl
// register scan — ONE __syncthreads total.
// NEW vs R10: the per-row binary search is done by ONE lane per row (lane 0
// -> row0, lane 1 -> row1) and broadcast via shfl, halving the dependent
// smem-load chain between the barrier and the first token LDG.
// ---------------------------------------------------------------------------
__global__ void __launch_bounds__(256, 8)
k_fused(const float4* __restrict__ tokens,
        const int*    __restrict__ counts,
        const float*  __restrict__ scales,
        float*        __restrict__ out) {
    __shared__ int s_in_start[NSEG];
    __shared__ int s_out_start[NSEG + 1];

    const int t = threadIdx.x;
    const int lane = t & 31;
    float4* __restrict__ out4 = (float4*)out;

    if (t < 32) {
        const int base = t * 4;
        // table A: input order (flat r*E+e) — contiguous, one LDG.128
        const int4 av = __ldg((const int4*)(counts + base));
        // table B: output order s = e*R+r  ->  count index (s&7)*E + (s>>3)
        const int b0 = __ldg(&counts[((base + 0) & 7) * N_EXPERTS + ((base + 0) >> 3)]);
        const int b1 = __ldg(&counts[((base + 1) & 7) * N_EXPERTS + ((base + 1) >> 3)]);
        const int b2 = __ldg(&counts[((base + 2) & 7) * N_EXPERTS + ((base + 2) >> 3)]);
        const int b3 = __ldg(&counts[((base + 3) & 7) * N_EXPERTS + ((base + 3) >> 3)]);

        const int sumA = av.x + av.y + av.z + av.w;
        const int sumB = b0 + b1 + b2 + b3;
        int exA = warp_exscan(sumA, t);
        int exB = warp_exscan(sumB, t);

        s_in_start[base + 0] = exA;
        s_in_start[base + 1] = exA + av.x;
        s_in_start[base + 2] = exA + av.x + av.y;
        s_in_start[base + 3] = exA + av.x + av.y + av.z;

        s_out_start[base + 0] = exB;
        s_out_start[base + 1] = exB + b0;
        s_out_start[base + 2] = exB + b0 + b1;
        s_out_start[base + 3] = exB + b0 + b1 + b2;
        if (t == 31) s_out_start[NSEG] = N_TOKENS;
    }
    // expert_token_num (block 0, warp 1 — overlaps warp 0's scan)
    if (blockIdx.x == 0 && t >= 32 && t < 32 + N_EXPERTS) {
        const int e = t - 32;
        int sum = 0;
        #pragma unroll
        for (int r = 0; r < N_RANKS; ++r) sum += __ldg(&counts[r * N_EXPERTS + e]);
        out[OFF_ETN + e] = (float)sum;
    }
    __syncthreads();   // the ONLY barrier

    const int row0 = blockIdx.x * 2;

    // Lane-split search: lane k (k<2) of each warp searches row0+k; results
    // broadcast via shfl. Halves the dependent LDS chain before the loads.
    int my_src = 0;
    if (lane < 2) {
        const int row = row0 + lane;
        int lo = 0, hi = NSEG;
        #pragma unroll 7
        while (hi - lo > 1) {
            int mid = (lo + hi) >> 1;
            if (s_out_start[mid] <= row) lo = mid; else hi = mid;
        }
        const int e = lo >> 3;            // lo / N_RANKS
        const int r = lo & 7;             // lo % N_RANKS
        my_src = s_in_start[r * N_EXPERTS + e] + (row - s_out_start[lo]);
    }
    const int src0 = __shfl_sync(0xffffffffu, my_src, 0);
    const int src1 = __shfl_sync(0xffffffffu, my_src, 1);

    const float4* __restrict__ in0 = tokens + (size_t)src0 * VEC_PER_ROW;
    const float4* __restrict__ in1 = tokens + (size_t)src1 * VEC_PER_ROW;
    float4* __restrict__ o0 = out4 + (size_t)row0 * VEC_PER_ROW;
    float4* __restrict__ o1 = o0 + VEC_PER_ROW;

    // 4 independent front-batched streaming loads (read-once).
    float4 a = __ldcs(&in0[t]);
    float4 b = __ldcs(&in0[t + 256]);
    float4 c = __ldcs(&in1[t]);
    float4 d = __ldcs(&in1[t + 256]);

    // Scale + idx inline (threads 0/1 of the block, one row each).
    if (t < 2) {
        const int row = row0 + t;
        const int s   = (t == 0) ? src0 : src1;
        out[OFF_SCALES + row] = __ldg(&scales[s]);
        out[OFF_IDX + row]    = (float)s;
    }

    // Streaming stores (write-once, never re-read).
    __stcs(&o0[t],       a);
    __stcs(&o0[t + 256], b);
    __stcs(&o1[t],       c);
    __stcs(&o1[t + 256], d);
}

// ---------------------------------------------------------------------------
extern "C" void kernel_launch(void* const* d_in, const int* in_sizes, int n_in,
                              void* d_out, int out_size) {
    const float* tokens = (const float*)d_in[0];
    const int*   counts = (const int*)d_in[1];     // [N_RANKS, N_EXPERTS]
    const float* scales = (const float*)d_in[2];
    // d_in[3] = expert_token_num_type (1), d_in[4] = idx_type (0) — fixed.
    float* out = (float*)d_out;

    k_fused<<<N_TOKENS / 2, 256>>>((const float4*)tokens, counts, scales, out);
}